// round 14
// baseline (speedup 1.0000x reference)
#include <cuda_runtime.h>
#include <cuda_fp16.h>
#include <cstdint>

// Flow_68015102099543: fused repack+conv, self-synchronized per batch.
// Phase 1: every CTA repacks a 380-pixel chunk of ITS batch z from fp32 NCHW x
//          into g_xh [4][458][484][16] fp16 pixel-major (halo never written ->
//          stays .bss zero = baked-in padding).
// Sync:    all threads __threadfence(); barrier; tid0 atomicAdd(done[z]) and
//          spins until done[z]==570. Batch z's 570 conv CTAs ARE its 570 repack
//          chunks; residency (740) >= cohort (570) -> deadlock-free.
// Phase 2: R12's proven conv body (32.0us measured): cp.async staging with no
//          predication/conversion, pixel-permuted B fragments, float4 epilogue.

#define HH 450
#define WW 480
#define HW (HH * WW)

#define HP_H 458
#define HP_W 484

#define CTA_H 8
#define CTA_W 48
#define HSX 10
#define NWS 50
#define ROWU 148
#define ROWB (ROWU * 16)
#define PXPB 380          // pixels repacked per CTA (380*570 >= 216000)
#define COHORT 570        // CTAs (= chunks) per batch

__device__ uint4 g_xh[(size_t)4 * HP_H * HP_W * 2];   // 28.4 MB, zero-init .bss
__device__ int   g_done[4];

__device__ __forceinline__ uint32_t smem_u32(const void* p) {
    return (uint32_t)__cvta_generic_to_shared(p);
}

__device__ __forceinline__ void ldsm_x4(uint32_t& r0, uint32_t& r1, uint32_t& r2, uint32_t& r3,
                                        uint32_t a) {
    asm volatile("ldmatrix.sync.aligned.m8n8.x4.shared.b16 {%0,%1,%2,%3}, [%4];"
                 : "=r"(r0), "=r"(r1), "=r"(r2), "=r"(r3) : "r"(a));
}

__device__ __forceinline__ void mma_fp16(float* d, const uint32_t* a,
                                         uint32_t b0, uint32_t b1) {
    asm volatile("mma.sync.aligned.m16n8k16.row.col.f32.f16.f16.f32 "
                 "{%0,%1,%2,%3}, {%4,%5,%6,%7}, {%8,%9}, {%0,%1,%2,%3};"
                 : "+f"(d[0]), "+f"(d[1]), "+f"(d[2]), "+f"(d[3])
                 : "r"(a[0]), "r"(a[1]), "r"(a[2]), "r"(a[3]), "r"(b0), "r"(b1));
}

__device__ __forceinline__ void cp16(uint32_t dst, const void* src) {
    asm volatile("cp.async.ca.shared.global [%0], [%1], 16;"
                 :: "r"(dst), "l"(src) : "memory");
}

__device__ __forceinline__ uint32_t unit_of(int w_s, int half_) {
    int sg = w_s + 2 * (w_s >> 2);
    return (uint32_t)(2 * sg + (half_ ^ ((sg >> 2) & 1)));
}

__global__ void zero_flags_kernel() {
    if (threadIdx.x < 4) g_done[threadIdx.x] = 0;
}

__global__ void __launch_bounds__(256, 5) flow_fused_kernel(
    const float* __restrict__ x,      // [4,16,450,480]
    const float* __restrict__ comb,   // [16,144]
    const float* __restrict__ bias,   // [16]
    float* __restrict__ out)          // [4,16,450,480]
{
    __shared__ uint4 xs4[HSX * ROWU];         // 23680 B
    __shared__ uint4 ws4[9 * 16 * 2];         // 4608 B

    const int tid = threadIdx.x;
    const int b  = blockIdx.z;
    const int h0 = blockIdx.y * CTA_H;
    const int w0 = blockIdx.x * CTA_W;
    const int chunk = blockIdx.y * 10 + blockIdx.x;      // 0..569 within batch

    // ---- phase 1: repack this CTA's 380-pixel chunk of batch b ----
    {
        const int base = chunk * PXPB;
#pragma unroll
        for (int k = 0; k < 2; k++) {
            int r = k * 256 + tid;
            int px = base + r;
            if (r < PXPB && px < HW) {
                int h = px / WW;
                int w = px - h * WW;
                const float* src = x + (size_t)(b * 16) * HW + px;
                uint32_t pk[8];
#pragma unroll
                for (int cc = 0; cc < 8; cc++) {
                    float v0 = __ldg(src + (size_t)(2 * cc)     * HW);
                    float v1 = __ldg(src + (size_t)(2 * cc + 1) * HW);
                    __half2 h2 = __floats2half2_rn(v0, v1);
                    pk[cc] = *(uint32_t*)&h2;
                }
                uint4* dst = &g_xh[((size_t)(b * HP_H + h + 1) * HP_W + (w + 1)) * 2];
                dst[0] = make_uint4(pk[0], pk[1], pk[2], pk[3]);
                dst[1] = make_uint4(pk[4], pk[5], pk[6], pk[7]);
            }
        }
    }

    // ---- stage weights while repack stores drain (reads comb only) ----
    for (int idx = tid; idx < 9 * 16 * 16; idx += 256) {
        int i = idx >> 8, o = (idx >> 4) & 15, c = idx & 15;
        float v = comb[o * 144 + i * 16 + c];
        int half_ = c >> 3;
        int phys = (i * 16 + o) * 2 + (half_ ^ ((o >> 2) & 1));
        ((__half*)ws4)[phys * 8 + (c & 7)] = __float2half(v);
    }

    // ---- publish + wait for the batch cohort ----
    __threadfence();              // every thread orders its own phase-1 stores
    __syncthreads();
    if (tid == 0) {
        atomicAdd(&g_done[b], 1);
        volatile int* p = &g_done[b];
        while (*p < COHORT) __nanosleep(64);
        __threadfence();          // acquire side
    }
    __syncthreads();

    // ---- phase 2: conv (proven R12 body) ----
    {
        const uint32_t xb = smem_u32(xs4);
        const size_t gbase = ((size_t)b * HP_H + h0) * HP_W + w0;
#pragma unroll
        for (int k = 0; k < 4; k++) {
            int u = k * 256 + tid;
            if (u < 1000) {
                int h_s = u / 100;
                int rem = u - h_s * 100;
                int w_s = rem >> 1;
                int half_ = rem & 1;
                const uint4* src = &g_xh[(gbase + h_s * HP_W + w_s) * 2 + half_];
                cp16(xb + (uint32_t)(h_s * ROWU + unit_of(w_s, half_)) * 16u, src);
            }
        }
        asm volatile("cp.async.commit_group;" ::: "memory");
        asm volatile("cp.async.wait_group 0;" ::: "memory");
    }
    __syncthreads();

    const int wid  = tid >> 5;
    const int lane = tid & 31;
    const int h = h0 + wid;
    if (h >= HH) return;          // whole-warp exit; no further barriers

    const int og = lane >> 2;
    const float b0v = __ldg(bias + og);
    const float b8v = __ldg(bias + 8 + og);
    float accA[3][4], accB[3][4];
#pragma unroll
    for (int p = 0; p < 3; p++) {
        accA[p][0] = b0v; accA[p][1] = b0v; accA[p][2] = b8v; accA[p][3] = b8v;
        accB[p][0] = b0v; accB[p][1] = b0v; accB[p][2] = b8v; accB[p][3] = b8v;
    }

    const uint32_t wbase = smem_u32(ws4);
    const uint32_t xbase = smem_u32(xs4);

    const int o_l   = ((lane >> 3) & 1) * 8 + (lane & 7);
    const int ahalf = (lane >> 4) & 1;
    const uint32_t aoff = (uint32_t)((o_l * 2 + (ahalf ^ ((o_l >> 2) & 1))) * 16);

    const int bp    = lane & 7;
    const int fbp   = (bp & 1) | ((bp >> 1) << 2);   // f = {0,1,4,5,8,9,12,13}
    const int qset  = (lane >> 4) & 1;
    const int bhalf = (lane >> 3) & 1;

#pragma unroll
    for (int i = 0; i < 9; i++) {
        const int dy = i / 3, dx = i % 3;
        uint32_t a[4];
        ldsm_x4(a[0], a[1], a[2], a[3], wbase + (uint32_t)i * 512u + aoff);
        const uint32_t rowoff = (uint32_t)((wid + dy) * ROWB);
#pragma unroll
        for (int p = 0; p < 3; p++) {
            const int w_s = p * 16 + dx + fbp + 2 * qset;
            const uint32_t addr = xbase + rowoff + unit_of(w_s, bhalf) * 16u;
            uint32_t r0, r1, r2, r3;
            ldsm_x4(r0, r1, r2, r3, addr);
            mma_fp16(accA[p], a, r0, r1);
            mma_fp16(accB[p], a, r2, r3);
        }
    }

    const int j = lane & 3;
    float* op0 = out + ((((size_t)b * 16 + og) * HH + h) * WW + w0 + 4 * j);
    float* op8 = op0 + (size_t)8 * HW;
#pragma unroll
    for (int p = 0; p < 3; p++) {
        float4 v0; v0.x = accA[p][0]; v0.y = accA[p][1]; v0.z = accB[p][0]; v0.w = accB[p][1];
        float4 v8; v8.x = accA[p][2]; v8.y = accA[p][3]; v8.z = accB[p][2]; v8.w = accB[p][3];
        *(float4*)(op0 + p * 16) = v0;
        *(float4*)(op8 + p * 16) = v8;
    }
}

extern "C" void kernel_launch(void* const* d_in, const int* in_sizes, int n_in,
                              void* d_out, int out_size) {
    const float* x    = (const float*)d_in[0];
    const float* comb = (const float*)d_in[1];
    const float* bias = (const float*)d_in[2];
    float* out = (float*)d_out;

    zero_flags_kernel<<<1, 32>>>();
    dim3 grid(10, 57, 4);                       // bid = x + 10y + 570z: batch cohorts contiguous
    flow_fused_kernel<<<grid, 256>>>(x, comb, bias, out);
}

// round 15
// speedup vs baseline: 1.1110x; 1.1110x over previous
#include <cuda_runtime.h>
#include <cuda_fp16.h>
#include <cstdint>

// Flow_68015102099543: fused repack+conv, front-loaded producer cohort.
// Phase 1 (z==0 CTAs only, bids 0..569): CTA c repacks pixel chunk c
//   [c*380, c*380+380) for ALL FOUR batches from fp32 NCHW x into
//   g_xh [4][458][484][16] fp16 pixel-major (halo never written -> .bss zero).
//   Unconditional (no waits) -> the single flag depends only on this cohort
//   -> deadlock-free at any occupancy / schedule.
// Sync: one global counter; every CTA's conv waits done==570.
// Phase 2: R12's proven conv body (32.0us measured): cp.async staging,
//   pixel-permuted B fragments, coalesced float4 epilogue.

#define HH 450
#define WW 480
#define HW (HH * WW)

#define HP_H 458
#define HP_W 484

#define CTA_H 8
#define CTA_W 48
#define HSX 10
#define NWS 50
#define ROWU 148
#define ROWB (ROWU * 16)
#define PXPB 380          // pixels per chunk (380*570 = 216600 >= 216000)
#define NCHUNK 570

__device__ uint4 g_xh[(size_t)4 * HP_H * HP_W * 2];   // 28.4 MB, zero-init .bss
__device__ int   g_done;

__device__ __forceinline__ uint32_t smem_u32(const void* p) {
    return (uint32_t)__cvta_generic_to_shared(p);
}

__device__ __forceinline__ void ldsm_x4(uint32_t& r0, uint32_t& r1, uint32_t& r2, uint32_t& r3,
                                        uint32_t a) {
    asm volatile("ldmatrix.sync.aligned.m8n8.x4.shared.b16 {%0,%1,%2,%3}, [%4];"
                 : "=r"(r0), "=r"(r1), "=r"(r2), "=r"(r3) : "r"(a));
}

__device__ __forceinline__ void mma_fp16(float* d, const uint32_t* a,
                                         uint32_t b0, uint32_t b1) {
    asm volatile("mma.sync.aligned.m16n8k16.row.col.f32.f16.f16.f32 "
                 "{%0,%1,%2,%3}, {%4,%5,%6,%7}, {%8,%9}, {%0,%1,%2,%3};"
                 : "+f"(d[0]), "+f"(d[1]), "+f"(d[2]), "+f"(d[3])
                 : "r"(a[0]), "r"(a[1]), "r"(a[2]), "r"(a[3]), "r"(b0), "r"(b1));
}

__device__ __forceinline__ void cp16(uint32_t dst, const void* src) {
    asm volatile("cp.async.ca.shared.global [%0], [%1], 16;"
                 :: "r"(dst), "l"(src) : "memory");
}

__device__ __forceinline__ uint32_t unit_of(int w_s, int half_) {
    int sg = w_s + 2 * (w_s >> 2);
    return (uint32_t)(2 * sg + (half_ ^ ((sg >> 2) & 1)));
}

__global__ void zero_flags_kernel() {
    if (threadIdx.x == 0) g_done = 0;
}

__global__ void __launch_bounds__(256, 5) flow_fused2_kernel(
    const float* __restrict__ x,      // [4,16,450,480]
    const float* __restrict__ comb,   // [16,144]
    const float* __restrict__ bias,   // [16]
    float* __restrict__ out)          // [4,16,450,480]
{
    __shared__ uint4 xs4[HSX * ROWU];         // 23680 B
    __shared__ uint4 ws4[9 * 16 * 2];         // 4608 B

    const int tid = threadIdx.x;
    const int b  = blockIdx.z;
    const int h0 = blockIdx.y * CTA_H;
    const int w0 = blockIdx.x * CTA_W;

    // ---- phase 1: z==0 cohort repacks its chunk for ALL batches ----
    if (b == 0) {
        const int chunk = blockIdx.y * 10 + blockIdx.x;     // 0..569
        const int base  = chunk * PXPB;
#pragma unroll
        for (int b4 = 0; b4 < 4; b4++) {
#pragma unroll
            for (int k = 0; k < 2; k++) {
                int r = k * 256 + tid;
                int px = base + r;
                if (r < PXPB && px < HW) {
                    int h = px / WW;
                    int w = px - h * WW;
                    const float* src = x + (size_t)(b4 * 16) * HW + px;
                    uint32_t pk[8];
#pragma unroll
                    for (int cc = 0; cc < 8; cc++) {
                        float v0 = __ldg(src + (size_t)(2 * cc)     * HW);
                        float v1 = __ldg(src + (size_t)(2 * cc + 1) * HW);
                        __half2 h2 = __floats2half2_rn(v0, v1);
                        pk[cc] = *(uint32_t*)&h2;
                    }
                    uint4* dst = &g_xh[((size_t)(b4 * HP_H + h + 1) * HP_W + (w + 1)) * 2];
                    dst[0] = make_uint4(pk[0], pk[1], pk[2], pk[3]);
                    dst[1] = make_uint4(pk[4], pk[5], pk[6], pk[7]);
                }
            }
        }
    }

    // ---- stage weights (all CTAs; reads comb only) ----
    for (int idx = tid; idx < 9 * 16 * 16; idx += 256) {
        int i = idx >> 8, o = (idx >> 4) & 15, c = idx & 15;
        float v = comb[o * 144 + i * 16 + c];
        int half_ = c >> 3;
        int phys = (i * 16 + o) * 2 + (half_ ^ ((o >> 2) & 1));
        ((__half*)ws4)[phys * 8 + (c & 7)] = __float2half(v);
    }

    // ---- publish (producers) + wait (everyone) ----
    __threadfence();              // order each thread's phase-1 stores
    __syncthreads();
    if (tid == 0) {
        if (b == 0) atomicAdd(&g_done, 1);
        volatile int* p = &g_done;
        while (*p < NCHUNK) __nanosleep(256);
        __threadfence();          // acquire
    }
    __syncthreads();

    // ---- phase 2: conv (proven R12 body) ----
    {
        const uint32_t xb = smem_u32(xs4);
        const size_t gbase = ((size_t)b * HP_H + h0) * HP_W + w0;
#pragma unroll
        for (int k = 0; k < 4; k++) {
            int u = k * 256 + tid;
            if (u < 1000) {
                int h_s = u / 100;
                int rem = u - h_s * 100;
                int w_s = rem >> 1;
                int half_ = rem & 1;
                const uint4* src = &g_xh[(gbase + h_s * HP_W + w_s) * 2 + half_];
                cp16(xb + (uint32_t)(h_s * ROWU + unit_of(w_s, half_)) * 16u, src);
            }
        }
        asm volatile("cp.async.commit_group;" ::: "memory");
        asm volatile("cp.async.wait_group 0;" ::: "memory");
    }
    __syncthreads();

    const int wid  = tid >> 5;
    const int lane = tid & 31;
    const int h = h0 + wid;
    if (h >= HH) return;          // whole-warp exit; no further barriers

    const int og = lane >> 2;
    const float b0v = __ldg(bias + og);
    const float b8v = __ldg(bias + 8 + og);
    float accA[3][4], accB[3][4];
#pragma unroll
    for (int p = 0; p < 3; p++) {
        accA[p][0] = b0v; accA[p][1] = b0v; accA[p][2] = b8v; accA[p][3] = b8v;
        accB[p][0] = b0v; accB[p][1] = b0v; accB[p][2] = b8v; accB[p][3] = b8v;
    }

    const uint32_t wbase = smem_u32(ws4);
    const uint32_t xbase = smem_u32(xs4);

    const int o_l   = ((lane >> 3) & 1) * 8 + (lane & 7);
    const int ahalf = (lane >> 4) & 1;
    const uint32_t aoff = (uint32_t)((o_l * 2 + (ahalf ^ ((o_l >> 2) & 1))) * 16);

    const int bp    = lane & 7;
    const int fbp   = (bp & 1) | ((bp >> 1) << 2);   // f = {0,1,4,5,8,9,12,13}
    const int qset  = (lane >> 4) & 1;
    const int bhalf = (lane >> 3) & 1;

#pragma unroll
    for (int i = 0; i < 9; i++) {
        const int dy = i / 3, dx = i % 3;
        uint32_t a[4];
        ldsm_x4(a[0], a[1], a[2], a[3], wbase + (uint32_t)i * 512u + aoff);
        const uint32_t rowoff = (uint32_t)((wid + dy) * ROWB);
#pragma unroll
        for (int p = 0; p < 3; p++) {
            const int w_s = p * 16 + dx + fbp + 2 * qset;
            const uint32_t addr = xbase + rowoff + unit_of(w_s, bhalf) * 16u;
            uint32_t r0, r1, r2, r3;
            ldsm_x4(r0, r1, r2, r3, addr);
            mma_fp16(accA[p], a, r0, r1);
            mma_fp16(accB[p], a, r2, r3);
        }
    }

    const int j = lane & 3;
    float* op0 = out + ((((size_t)b * 16 + og) * HH + h) * WW + w0 + 4 * j);
    float* op8 = op0 + (size_t)8 * HW;
#pragma unroll
    for (int p = 0; p < 3; p++) {
        float4 v0; v0.x = accA[p][0]; v0.y = accA[p][1]; v0.z = accB[p][0]; v0.w = accB[p][1];
        float4 v8; v8.x = accA[p][2]; v8.y = accA[p][3]; v8.z = accB[p][2]; v8.w = accB[p][3];
        *(float4*)(op0 + p * 16) = v0;
        *(float4*)(op8 + p * 16) = v8;
    }
}

extern "C" void kernel_launch(void* const* d_in, const int* in_sizes, int n_in,
                              void* d_out, int out_size) {
    const float* x    = (const float*)d_in[0];
    const float* comb = (const float*)d_in[1];
    const float* bias = (const float*)d_in[2];
    float* out = (float*)d_out;

    zero_flags_kernel<<<1, 32>>>();
    dim3 grid(10, 57, 4);     // bid = x + 10y + 570z: producer cohort = bids 0..569
    flow_fused2_kernel<<<grid, 256>>>(x, comb, bias, out);
}

// round 16
// speedup vs baseline: 1.2498x; 1.1249x over previous
#include <cuda_runtime.h>
#include <cuda_fp16.h>
#include <cstdint>

// Flow_68015102099543: fused repack+conv with PER-ROW ready flags (pipelined).
// Producer: CTA chunk c=10y+x (<450) of batch z repacks input row r=c of its
//   batch into g_xh [4][458][484][16] fp16 (halo rows/cols never written ->
//   .bss zero). Publishes g_rdy[b*450+r]. Production is UNCONDITIONAL and
//   precedes any wait -> progress guaranteed (consumer bid B waits only on
//   bids <= B+8; only top-8 resident CTAs can wait on unlaunched producers).
// Consumer: same CTA then polls the <=10 row flags its tile needs and runs the
//   proven R12 conv body (32.0us measured): cp.async staging, pixel-permuted
//   B fragments, coalesced float4 epilogue.

#define HH 450
#define WW 480
#define HW (HH * WW)

#define HP_H 458
#define HP_W 484

#define CTA_H 8
#define CTA_W 48
#define HSX 10
#define ROWU 148
#define ROWB (ROWU * 16)

__device__ uint4 g_xh[(size_t)4 * HP_H * HP_W * 2];   // 28.4 MB, zero-init .bss
__device__ int   g_rdy[4 * HH];                        // per (batch,row) flags

__device__ __forceinline__ uint32_t smem_u32(const void* p) {
    return (uint32_t)__cvta_generic_to_shared(p);
}

__device__ __forceinline__ void ldsm_x4(uint32_t& r0, uint32_t& r1, uint32_t& r2, uint32_t& r3,
                                        uint32_t a) {
    asm volatile("ldmatrix.sync.aligned.m8n8.x4.shared.b16 {%0,%1,%2,%3}, [%4];"
                 : "=r"(r0), "=r"(r1), "=r"(r2), "=r"(r3) : "r"(a));
}

__device__ __forceinline__ void mma_fp16(float* d, const uint32_t* a,
                                         uint32_t b0, uint32_t b1) {
    asm volatile("mma.sync.aligned.m16n8k16.row.col.f32.f16.f16.f32 "
                 "{%0,%1,%2,%3}, {%4,%5,%6,%7}, {%8,%9}, {%0,%1,%2,%3};"
                 : "+f"(d[0]), "+f"(d[1]), "+f"(d[2]), "+f"(d[3])
                 : "r"(a[0]), "r"(a[1]), "r"(a[2]), "r"(a[3]), "r"(b0), "r"(b1));
}

__device__ __forceinline__ void cp16(uint32_t dst, const void* src) {
    asm volatile("cp.async.ca.shared.global [%0], [%1], 16;"
                 :: "r"(dst), "l"(src) : "memory");
}

__device__ __forceinline__ uint32_t unit_of(int w_s, int half_) {
    int sg = w_s + 2 * (w_s >> 2);
    return (uint32_t)(2 * sg + (half_ ^ ((sg >> 2) & 1)));
}

__global__ void zero_flags_kernel() {
    int i = blockIdx.x * 256 + threadIdx.x;
    if (i < 4 * HH) g_rdy[i] = 0;
}

__global__ void __launch_bounds__(256, 5) flow_rowpipe_kernel(
    const float* __restrict__ x,      // [4,16,450,480]
    const float* __restrict__ comb,   // [16,144]
    const float* __restrict__ bias,   // [16]
    float* __restrict__ out)          // [4,16,450,480]
{
    __shared__ uint4 xs4[HSX * ROWU];         // 23680 B
    __shared__ uint4 ws4[9 * 16 * 2];         // 4608 B

    const int tid = threadIdx.x;
    const int b  = blockIdx.z;
    const int h0 = blockIdx.y * CTA_H;
    const int w0 = blockIdx.x * CTA_W;
    const int chunk = blockIdx.y * 10 + blockIdx.x;      // 0..569 within batch

    // ---- phase 1: produce input row r = chunk of batch b (if it exists) ----
    if (chunk < HH) {
        const int r = chunk;
#pragma unroll
        for (int k = 0; k < 2; k++) {
            int px = k * 256 + tid;
            if (px < WW) {
                const float* src = x + ((size_t)(b * 16) * HH + r) * WW + px;
                uint32_t pk[8];
#pragma unroll
                for (int cc = 0; cc < 8; cc++) {
                    float v0 = __ldg(src + (size_t)(2 * cc)     * HW);
                    float v1 = __ldg(src + (size_t)(2 * cc + 1) * HW);
                    __half2 h2 = __floats2half2_rn(v0, v1);
                    pk[cc] = *(uint32_t*)&h2;
                }
                uint4* dst = &g_xh[((size_t)(b * HP_H + r + 1) * HP_W + (px + 1)) * 2];
                dst[0] = make_uint4(pk[0], pk[1], pk[2], pk[3]);
                dst[1] = make_uint4(pk[4], pk[5], pk[6], pk[7]);
            }
        }
    }

    // ---- stage weights (reads comb only) ----
    for (int idx = tid; idx < 9 * 16 * 16; idx += 256) {
        int i = idx >> 8, o = (idx >> 4) & 15, c = idx & 15;
        float v = comb[o * 144 + i * 16 + c];
        int half_ = c >> 3;
        int phys = (i * 16 + o) * 2 + (half_ ^ ((o >> 2) & 1));
        ((__half*)ws4)[phys * 8 + (c & 7)] = __float2half(v);
    }

    // ---- publish own row BEFORE any wait ----
    __threadfence();              // order this thread's phase-1 stores
    __syncthreads();              // all 256 threads' stores ordered before flag
    if (chunk < HH && tid == 0)
        atomicExch(&g_rdy[b * HH + chunk], 1);

    // ---- wait for the <=10 rows this tile needs (parallel poll) ----
    {
        const int lo = (h0 - 1 > 0) ? (h0 - 1) : 0;
        const int hi = (h0 + 8 < HH - 1) ? (h0 + 8) : (HH - 1);
        const int cnt = hi - lo + 1;
        if (tid < cnt) {
            volatile int* f = &g_rdy[b * HH + lo + tid];
            while (*f == 0) __nanosleep(64);
            __threadfence();      // acquire: producer stores -> our reads
        }
        __syncthreads();
    }

    // ---- phase 2: conv (proven R12 body, byte-identical) ----
    {
        const uint32_t xb = smem_u32(xs4);
        const size_t gbase = ((size_t)b * HP_H + h0) * HP_W + w0;
#pragma unroll
        for (int k = 0; k < 4; k++) {
            int u = k * 256 + tid;
            if (u < 1000) {
                int h_s = u / 100;
                int rem = u - h_s * 100;
                int w_s = rem >> 1;
                int half_ = rem & 1;
                const uint4* src = &g_xh[(gbase + h_s * HP_W + w_s) * 2 + half_];
                cp16(xb + (uint32_t)(h_s * ROWU + unit_of(w_s, half_)) * 16u, src);
            }
        }
        asm volatile("cp.async.commit_group;" ::: "memory");
        asm volatile("cp.async.wait_group 0;" ::: "memory");
    }
    __syncthreads();

    const int wid  = tid >> 5;
    const int lane = tid & 31;
    const int h = h0 + wid;
    if (h >= HH) return;          // whole-warp exit; no further barriers

    const int og = lane >> 2;
    const float b0v = __ldg(bias + og);
    const float b8v = __ldg(bias + 8 + og);
    float accA[3][4], accB[3][4];
#pragma unroll
    for (int p = 0; p < 3; p++) {
        accA[p][0] = b0v; accA[p][1] = b0v; accA[p][2] = b8v; accA[p][3] = b8v;
        accB[p][0] = b0v; accB[p][1] = b0v; accB[p][2] = b8v; accB[p][3] = b8v;
    }

    const uint32_t wbase = smem_u32(ws4);
    const uint32_t xbase = smem_u32(xs4);

    const int o_l   = ((lane >> 3) & 1) * 8 + (lane & 7);
    const int ahalf = (lane >> 4) & 1;
    const uint32_t aoff = (uint32_t)((o_l * 2 + (ahalf ^ ((o_l >> 2) & 1))) * 16);

    const int bp    = lane & 7;
    const int fbp   = (bp & 1) | ((bp >> 1) << 2);   // f = {0,1,4,5,8,9,12,13}
    const int qset  = (lane >> 4) & 1;
    const int bhalf = (lane >> 3) & 1;

#pragma unroll
    for (int i = 0; i < 9; i++) {
        const int dy = i / 3, dx = i % 3;
        uint32_t a[4];
        ldsm_x4(a[0], a[1], a[2], a[3], wbase + (uint32_t)i * 512u + aoff);
        const uint32_t rowoff = (uint32_t)((wid + dy) * ROWB);
#pragma unroll
        for (int p = 0; p < 3; p++) {
            const int w_s = p * 16 + dx + fbp + 2 * qset;
            const uint32_t addr = xbase + rowoff + unit_of(w_s, bhalf) * 16u;
            uint32_t r0, r1, r2, r3;
            ldsm_x4(r0, r1, r2, r3, addr);
            mma_fp16(accA[p], a, r0, r1);
            mma_fp16(accB[p], a, r2, r3);
        }
    }

    const int j = lane & 3;
    float* op0 = out + ((((size_t)b * 16 + og) * HH + h) * WW + w0 + 4 * j);
    float* op8 = op0 + (size_t)8 * HW;
#pragma unroll
    for (int p = 0; p < 3; p++) {
        float4 v0; v0.x = accA[p][0]; v0.y = accA[p][1]; v0.z = accB[p][0]; v0.w = accB[p][1];
        float4 v8; v8.x = accA[p][2]; v8.y = accA[p][3]; v8.z = accB[p][2]; v8.w = accB[p][3];
        *(float4*)(op0 + p * 16) = v0;
        *(float4*)(op8 + p * 16) = v8;
    }
}

extern "C" void kernel_launch(void* const* d_in, const int* in_sizes, int n_in,
                              void* d_out, int out_size) {
    const float* x    = (const float*)d_in[0];
    const float* comb = (const float*)d_in[1];
    const float* bias = (const float*)d_in[2];
    float* out = (float*)d_out;

    zero_flags_kernel<<<8, 256>>>();
    dim3 grid(10, 57, 4);     // bid = x + 10y + 570z
    flow_rowpipe_kernel<<<grid, 256>>>(x, comb, bias, out);
}